// round 2
// baseline (speedup 1.0000x reference)
#include <cuda_runtime.h>
#include <math.h>

#define DM   1024
#define NH   16
#define DH   64
#define DFF  4096
#define BB   8
#define SS   1024
#define MTOK (BB*SS)

// ---------------- scratch (static device allocations) ----------------
__device__ float g_x0  [MTOK*DM];      // x + step_embed
__device__ float g_qkv [MTOK*3*DM];    // qkv projection
__device__ float g_attn[MTOK*DM];      // attention output (head-concat)
__device__ float g_proj[MTOK*DM];      // out projection
__device__ float g_x1  [MTOK*DM];      // after LN1
__device__ float g_h   [MTOK*DFF];     // ffn hidden (gelu)
__device__ float g_ffn [MTOK*DM];      // ffn out

// ---------------- elementwise: x + step_embed[step] ----------------
__global__ void add_step_kernel(const float* __restrict__ x,
                                const float* __restrict__ se,
                                const int*   __restrict__ ts,
                                float* __restrict__ out)
{
    int i = blockIdx.x * blockDim.x + threadIdx.x;
    int step = ts[0];
    if (step > 15) step = 15;
    if (step < 0) step += 16;   // python negative-index semantics
    out[i] = x[i] + se[step * DM + (i & (DM - 1))];
}

// ---------------- SGEMM: C[M,N] = A[M,K] @ W[K,N] + bias (opt gelu) ----------------
__device__ __forceinline__ float gelu_exact(float v)
{
    return 0.5f * v * (1.0f + erff(v * 0.70710678118654752f));
}

template <int ACT>
__global__ void __launch_bounds__(256, 2)
sgemm_kernel(const float* __restrict__ A, const float* __restrict__ W,
             const float* __restrict__ bias, float* __restrict__ C,
             int Mdim, int Ndim, int Kdim)
{
    __shared__ float As[16][128];   // transposed A tile
    __shared__ float Bs[16][128];

    const int tid = threadIdx.x;
    const int tx = tid & 15;       // 0..15  -> 8 cols each
    const int ty = tid >> 4;       // 0..15  -> 8 rows each
    const int row0 = blockIdx.y * 128;
    const int col0 = blockIdx.x * 128;

    const int ar = tid >> 2;            // 0..63
    const int ac = (tid & 3) << 2;      // 0,4,8,12
    const int br = tid >> 5;            // 0..7
    const int bc = (tid & 31) << 2;     // 0..124

    const float* Aptr = A + (size_t)(row0 + ar) * Kdim + ac;
    const float* Wptr = W + (size_t)br * Ndim + col0 + bc;

    float acc[8][8];
#pragma unroll
    for (int i = 0; i < 8; i++)
#pragma unroll
        for (int j = 0; j < 8; j++) acc[i][j] = 0.f;

    for (int k0 = 0; k0 < Kdim; k0 += 16) {
        float4 a0 = *(const float4*)(Aptr + k0);
        float4 a1 = *(const float4*)(Aptr + k0 + (size_t)64 * Kdim);
        float4 b0 = *(const float4*)(Wptr + (size_t)k0 * Ndim);
        float4 b1 = *(const float4*)(Wptr + (size_t)(k0 + 8) * Ndim);

        As[ac + 0][ar] = a0.x; As[ac + 1][ar] = a0.y;
        As[ac + 2][ar] = a0.z; As[ac + 3][ar] = a0.w;
        As[ac + 0][ar + 64] = a1.x; As[ac + 1][ar + 64] = a1.y;
        As[ac + 2][ar + 64] = a1.z; As[ac + 3][ar + 64] = a1.w;
        *(float4*)&Bs[br][bc]     = b0;
        *(float4*)&Bs[br + 8][bc] = b1;
        __syncthreads();

#pragma unroll
        for (int k = 0; k < 16; k++) {
            float4 alo = *(const float4*)&As[k][ty * 8];
            float4 ahi = *(const float4*)&As[k][ty * 8 + 4];
            float4 blo = *(const float4*)&Bs[k][tx * 8];
            float4 bhi = *(const float4*)&Bs[k][tx * 8 + 4];
            float af[8] = {alo.x, alo.y, alo.z, alo.w, ahi.x, ahi.y, ahi.z, ahi.w};
            float bf[8] = {blo.x, blo.y, blo.z, blo.w, bhi.x, bhi.y, bhi.z, bhi.w};
#pragma unroll
            for (int i = 0; i < 8; i++)
#pragma unroll
                for (int j = 0; j < 8; j++)
                    acc[i][j] += af[i] * bf[j];
        }
        __syncthreads();
    }

#pragma unroll
    for (int i = 0; i < 8; i++) {
        size_t row = (size_t)(row0 + ty * 8 + i);
#pragma unroll
        for (int jj = 0; jj < 8; jj += 4) {
            int col = col0 + tx * 8 + jj;
            float4 v;
            v.x = acc[i][jj + 0] + bias[col + 0];
            v.y = acc[i][jj + 1] + bias[col + 1];
            v.z = acc[i][jj + 2] + bias[col + 2];
            v.w = acc[i][jj + 3] + bias[col + 3];
            if (ACT == 1) {
                v.x = gelu_exact(v.x); v.y = gelu_exact(v.y);
                v.z = gelu_exact(v.z); v.w = gelu_exact(v.w);
            }
            *(float4*)&C[row * Ndim + col] = v;
        }
    }
}

// ---------------- flash attention with rel-pos bias ----------------
// grid: (32 q-tiles of 32 rows, 16 heads, 8 batch); block: 256 threads
// thread map: tr = tid/32 (4 q-rows each: tr*4..+3), tc = tid%32
//   scores: keys {tc, tc+32} per key-tile of 64
//   PV:     dims {2tc, 2tc+1}
__global__ void __launch_bounds__(256)
attn_kernel(const float* __restrict__ qkv, const float* __restrict__ rpb,
            float* __restrict__ out)
{
    __shared__ __align__(16) float Qs[32 * 65];
    __shared__ __align__(16) float KPs[64 * 65];   // K tile, then reused for P
    __shared__ __align__(16) float Vs[64 * 66];
    __shared__ float rb[127];

    const int tid = threadIdx.x;
    const int qt = blockIdx.x;
    const int h  = blockIdx.y;
    const int b  = blockIdx.z;
    const int tc = tid & 31;
    const int tr = tid >> 5;

    if (tid < 127) rb[tid] = rpb[tid];

    const int qbase = qt * 32;
    const float scale = 0.125f;  // 1/sqrt(64)

    for (int t = tid; t < 32 * 64; t += 256) {
        int r = t >> 6, c = t & 63;
        Qs[r * 65 + c] =
            qkv[((size_t)(b * SS + qbase + r)) * 3072 + h * 64 + c] * scale;
    }

    float m[4], l[4], acc[4][2];
#pragma unroll
    for (int i = 0; i < 4; i++) {
        m[i] = -1e30f; l[i] = 0.f; acc[i][0] = 0.f; acc[i][1] = 0.f;
    }

    for (int kt = 0; kt < 16; kt++) {
        const int kbase = kt * 64;
        __syncthreads();   // prev-iter P/V reads done; Q load done (iter 0)
        for (int t = tid; t < 64 * 64; t += 256) {
            int r = t >> 6, c = t & 63;
            size_t base = ((size_t)(b * SS + kbase + r)) * 3072 + h * 64 + c;
            KPs[r * 65 + c] = qkv[base + 1024];
            Vs [r * 66 + c] = qkv[base + 2048];
        }
        __syncthreads();

        // scores
        float s0[4] = {0.f, 0.f, 0.f, 0.f};
        float s1[4] = {0.f, 0.f, 0.f, 0.f};
#pragma unroll 4
        for (int d = 0; d < 64; d++) {
            float k0v = KPs[tc * 65 + d];
            float k1v = KPs[(tc + 32) * 65 + d];
#pragma unroll
            for (int i = 0; i < 4; i++) {
                float qv = Qs[(tr * 4 + i) * 65 + d];
                s0[i] += qv * k0v;
                s1[i] += qv * k1v;
            }
        }
#pragma unroll
        for (int i = 0; i < 4; i++) {
            int qg = qbase + tr * 4 + i;
            int r0 = qg - (kbase + tc) + 63;       r0 = min(max(r0, 0), 126);
            int r1 = qg - (kbase + tc + 32) + 63;  r1 = min(max(r1, 0), 126);
            s0[i] += rb[r0];
            s1[i] += rb[r1];
        }

        __syncthreads();   // all K reads complete before P overwrites KPs

        // online softmax (shfl across the 32 lanes of the warp = one row group)
#pragma unroll
        for (int i = 0; i < 4; i++) {
            float mt = fmaxf(s0[i], s1[i]);
#pragma unroll
            for (int o = 16; o > 0; o >>= 1)
                mt = fmaxf(mt, __shfl_xor_sync(0xffffffffu, mt, o));
            float mn = fmaxf(m[i], mt);
            float ci = __expf(m[i] - mn);
            float p0 = __expf(s0[i] - mn);
            float p1 = __expf(s1[i] - mn);
            float ls = p0 + p1;
#pragma unroll
            for (int o = 16; o > 0; o >>= 1)
                ls += __shfl_xor_sync(0xffffffffu, ls, o);
            l[i] = l[i] * ci + ls;
            m[i] = mn;
            acc[i][0] *= ci;
            acc[i][1] *= ci;
            KPs[(tr * 4 + i) * 65 + tc]      = p0;
            KPs[(tr * 4 + i) * 65 + tc + 32] = p1;
        }
        __syncthreads();

        // PV accumulate
        const int d0 = tc * 2;
#pragma unroll 4
        for (int k = 0; k < 64; k++) {
            float2 v = *(const float2*)&Vs[k * 66 + d0];
#pragma unroll
            for (int i = 0; i < 4; i++) {
                float p = KPs[(tr * 4 + i) * 65 + k];
                acc[i][0] += p * v.x;
                acc[i][1] += p * v.y;
            }
        }
    }

#pragma unroll
    for (int i = 0; i < 4; i++) {
        float inv = 1.f / l[i];
        size_t tok = (size_t)(b * SS + qbase + tr * 4 + i);
        out[tok * DM + h * 64 + tc * 2]     = acc[i][0] * inv;
        out[tok * DM + h * 64 + tc * 2 + 1] = acc[i][1] * inv;
    }
}

// ---------------- residual + layernorm ----------------
__global__ void __launch_bounds__(256)
ln_res_kernel(const float* __restrict__ a, const float* __restrict__ r,
              const float* __restrict__ g, const float* __restrict__ bt,
              float* __restrict__ out)
{
    __shared__ float red[8];
    const int row = blockIdx.x;
    const int tid = threadIdx.x;
    const float* pa = a + (size_t)row * DM;
    const float* pr = r + (size_t)row * DM;

    float v[4];
    float sum = 0.f;
#pragma unroll
    for (int j = 0; j < 4; j++) {
        int c = tid + j * 256;
        v[j] = pa[c] + pr[c];
        sum += v[j];
    }
#pragma unroll
    for (int o = 16; o > 0; o >>= 1) sum += __shfl_xor_sync(0xffffffffu, sum, o);
    if ((tid & 31) == 0) red[tid >> 5] = sum;
    __syncthreads();
    float tot = 0.f;
#pragma unroll
    for (int w = 0; w < 8; w++) tot += red[w];
    const float mean = tot * (1.f / (float)DM);

    float sq = 0.f;
#pragma unroll
    for (int j = 0; j < 4; j++) {
        float d = v[j] - mean;
        sq += d * d;
    }
    __syncthreads();   // red reuse
#pragma unroll
    for (int o = 16; o > 0; o >>= 1) sq += __shfl_xor_sync(0xffffffffu, sq, o);
    if ((tid & 31) == 0) red[tid >> 5] = sq;
    __syncthreads();
    float vtot = 0.f;
#pragma unroll
    for (int w = 0; w < 8; w++) vtot += red[w];
    const float inv = rsqrtf(vtot * (1.f / (float)DM) + 1e-5f);

#pragma unroll
    for (int j = 0; j < 4; j++) {
        int c = tid + j * 256;
        out[(size_t)row * DM + c] = (v[j] - mean) * inv * g[c] + bt[c];
    }
}

// ---------------- launch ----------------
extern "C" void kernel_launch(void* const* d_in, const int* in_sizes, int n_in,
                              void* d_out, int out_size)
{
    const float* x     = (const float*)d_in[0];
    const float* se    = (const float*)d_in[1];
    const float* qkv_w = (const float*)d_in[2];
    const float* qkv_b = (const float*)d_in[3];
    const float* out_w = (const float*)d_in[4];
    const float* out_b = (const float*)d_in[5];
    const float* rpb   = (const float*)d_in[6];
    const float* w1    = (const float*)d_in[7];
    const float* b1    = (const float*)d_in[8];
    const float* w2    = (const float*)d_in[9];
    const float* b2    = (const float*)d_in[10];
    const float* ln1g  = (const float*)d_in[11];
    const float* ln1b  = (const float*)d_in[12];
    const float* ln2g  = (const float*)d_in[13];
    const float* ln2b  = (const float*)d_in[14];
    const int*   ts    = (const int*)d_in[15];
    float* out = (float*)d_out;

    float *x0, *qkv, *attn, *proj, *x1, *hbuf, *ffn;
    cudaGetSymbolAddress((void**)&x0,   g_x0);
    cudaGetSymbolAddress((void**)&qkv,  g_qkv);
    cudaGetSymbolAddress((void**)&attn, g_attn);
    cudaGetSymbolAddress((void**)&proj, g_proj);
    cudaGetSymbolAddress((void**)&x1,   g_x1);
    cudaGetSymbolAddress((void**)&hbuf, g_h);
    cudaGetSymbolAddress((void**)&ffn,  g_ffn);

    // 1) x0 = x + step_embed[step]
    add_step_kernel<<<(MTOK * DM) / 256, 256>>>(x, se, ts, x0);

    // 2) qkv = x0 @ qkv_w + qkv_b
    sgemm_kernel<0><<<dim3(3 * DM / 128, MTOK / 128), 256>>>(
        x0, qkv_w, qkv_b, qkv, MTOK, 3 * DM, DM);

    // 3) attention
    attn_kernel<<<dim3(SS / 32, NH, BB), 256>>>(qkv, rpb, attn);

    // 4) proj = attn @ out_w + out_b
    sgemm_kernel<0><<<dim3(DM / 128, MTOK / 128), 256>>>(
        attn, out_w, out_b, proj, MTOK, DM, DM);

    // 5) x1 = LN(x0 + proj)
    ln_res_kernel<<<MTOK, 256>>>(x0, proj, ln1g, ln1b, x1);

    // 6) h = gelu(x1 @ w1 + b1)
    sgemm_kernel<1><<<dim3(DFF / 128, MTOK / 128), 256>>>(
        x1, w1, b1, hbuf, MTOK, DFF, DM);

    // 7) ffn = h @ w2 + b2
    sgemm_kernel<0><<<dim3(DM / 128, MTOK / 128), 256>>>(
        hbuf, w2, b2, ffn, MTOK, DM, DFF);

    // 8) out = LN(x1 + ffn)
    ln_res_kernel<<<MTOK, 256>>>(x1, ffn, ln2g, ln2b, out);
}

// round 4
// speedup vs baseline: 1.7513x; 1.7513x over previous
#include <cuda_runtime.h>
#include <cuda_bf16.h>
#include <math.h>
#include <stdint.h>

#define DM   1024
#define NH   16
#define DFF  4096
#define BB   8
#define SS   1024
#define MTOK (BB*SS)
#define KP3   (3*DM)    // 3072  (split-K for K=1024)
#define KP3FF (3*DFF)   // 12288 (split-K for K=4096)

// ---------------- scratch ----------------
__device__ float g_x0  [MTOK*DM];
__device__ float g_qkv [MTOK*3*DM];
__device__ float g_proj[MTOK*DM];
__device__ float g_x1  [MTOK*DM];
__device__ float g_ffn [MTOK*DM];
__device__ __nv_bfloat16 g_x0s  [(size_t)MTOK*KP3];
__device__ __nv_bfloat16 g_attns[(size_t)MTOK*KP3];
__device__ __nv_bfloat16 g_x1s  [(size_t)MTOK*KP3];
__device__ __nv_bfloat16 g_hs   [(size_t)MTOK*KP3FF];
__device__ __nv_bfloat16 g_wqkvs[(size_t)(3*DM)*KP3];
__device__ __nv_bfloat16 g_wouts[(size_t)DM*KP3];
__device__ __nv_bfloat16 g_w1s  [(size_t)DFF*KP3];
__device__ __nv_bfloat16 g_w2s  [(size_t)DM*KP3FF];

// ---------------- asm helpers ----------------
__device__ __forceinline__ uint32_t smem_u32(const void* p) {
    uint32_t a;
    asm("{ .reg .u64 t; cvta.to.shared.u64 t, %1; cvt.u32.u64 %0, t; }" : "=r"(a) : "l"(p));
    return a;
}
#define CP_ASYNC16(saddr, gptr) \
    asm volatile("cp.async.cg.shared.global [%0], [%1], 16;" :: "r"(saddr), "l"(gptr))
#define CP_COMMIT() asm volatile("cp.async.commit_group;" ::: "memory")
#define CP_WAIT1()  asm volatile("cp.async.wait_group 1;" ::: "memory")
#define CP_WAIT0()  asm volatile("cp.async.wait_group 0;" ::: "memory")

#define LDM_X4(r0, r1, r2, r3, a) \
    asm volatile("ldmatrix.sync.aligned.m8n8.x4.shared.b16 {%0,%1,%2,%3}, [%4];" \
                 : "=r"(r0), "=r"(r1), "=r"(r2), "=r"(r3) : "r"(a))
#define LDM_X2(r0, r1, a) \
    asm volatile("ldmatrix.sync.aligned.m8n8.x2.shared.b16 {%0,%1}, [%2];" \
                 : "=r"(r0), "=r"(r1) : "r"(a))

#define MMA_BF16(d, a0, a1, a2, a3, b0, b1) \
    asm volatile("mma.sync.aligned.m16n8k16.row.col.f32.bf16.bf16.f32 " \
                 "{%0,%1,%2,%3}, {%4,%5,%6,%7}, {%8,%9}, {%0,%1,%2,%3};" \
                 : "+f"((d)[0]), "+f"((d)[1]), "+f"((d)[2]), "+f"((d)[3]) \
                 : "r"(a0), "r"(a1), "r"(a2), "r"(a3), "r"(b0), "r"(b1))

__device__ __forceinline__ float gelu_exact(float v) {
    return 0.5f * v * (1.0f + erff(v * 0.70710678118654752f));
}

// ---------------- GEMM via mma.sync (bf16, f32 accum) --------------------
// C[M,N] = A''[M,Kp] x B''t[N,Kp]. CTA 128x128, BK=32, 8 warps of 64x32.
// smem rows padded to 40 bf16 (80B stride) -> conflict-free ldmatrix.
#define STG_E   (128 * 40)          // elems per tile per stage
#define STG_B   (STG_E * 2)         // 10240 bytes
#define NSTAGE  3
#define GSMEM   (NSTAGE * STG_B * 2)  // 61440 bytes

template <int ACT>
__global__ void __launch_bounds__(256, 2)
gemm_mma(const __nv_bfloat16* __restrict__ A, const __nv_bfloat16* __restrict__ B,
         const float* __restrict__ bias, float* __restrict__ Cf,
         __nv_bfloat16* __restrict__ Cs, int Ndim, int Kp, int cs_slab)
{
    extern __shared__ __align__(128) char smem[];
    const uint32_t sA = smem_u32(smem);
    const uint32_t sB = sA + NSTAGE * STG_B;

    const int tid  = threadIdx.x;
    const int lane = tid & 31;
    const int wid  = tid >> 5;
    const int wm   = wid & 1;        // M half (64)
    const int wn   = wid >> 1;       // N quarter (32)
    const int row0 = blockIdx.y * 128;
    const int n0   = blockIdx.x * 128;

    // cp.async indices: each thread moves 2x16B for A and 2x16B for B per stage
    const int ldr0 = tid >> 2;               // rows 0..63
    const int ldkc = (tid & 3) * 16;         // byte offset within 64B k-chunk
    const __nv_bfloat16* gA = A + (size_t)(row0 + ldr0) * Kp;
    const __nv_bfloat16* gB = B + (size_t)(n0  + ldr0) * Kp;

    // ldmatrix source addresses (per stage add stage*STG_B)
    const uint32_t aLd = sA + ((wm * 64 + (lane & 15)) * 40 + (lane >> 4) * 8) * 2;
    const uint32_t bLd = sB + ((wn * 32 + (lane & 7)) * 40 + ((lane >> 3) & 1) * 8) * 2;

    float d[4][4][4];
#pragma unroll
    for (int i = 0; i < 4; i++)
#pragma unroll
        for (int j = 0; j < 4; j++)
#pragma unroll
            for (int c = 0; c < 4; c++) d[i][j][c] = 0.f;

    const int kTiles = Kp >> 5;   // BK=32

    // prefetch stages 0,1
#pragma unroll
    for (int s = 0; s < 2; s++) {
        const int k0 = s * 32;
#pragma unroll
        for (int i = 0; i < 2; i++) {
            int r = ldr0 + i * 64;
            uint32_t dstA = sA + s * STG_B + r * 80 + ldkc;
            uint32_t dstB = sB + s * STG_B + r * 80 + ldkc;
            CP_ASYNC16(dstA, (const char*)(gA + (size_t)i * 64 * Kp + k0) + ldkc);
            CP_ASYNC16(dstB, (const char*)(gB + (size_t)i * 64 * Kp + k0) + ldkc);
        }
        CP_COMMIT();
    }

    for (int kt = 0; kt < kTiles; kt++) {
        CP_WAIT1();
        __syncthreads();

        // prefetch stage kt+2
        if (kt + 2 < kTiles) {
            const int s = (kt + 2) % NSTAGE;
            const int k0 = (kt + 2) * 32;
#pragma unroll
            for (int i = 0; i < 2; i++) {
                int r = ldr0 + i * 64;
                uint32_t dstA = sA + s * STG_B + r * 80 + ldkc;
                uint32_t dstB = sB + s * STG_B + r * 80 + ldkc;
                CP_ASYNC16(dstA, (const char*)(gA + (size_t)i * 64 * Kp + k0) + ldkc);
                CP_ASYNC16(dstB, (const char*)(gB + (size_t)i * 64 * Kp + k0) + ldkc);
            }
        }
        CP_COMMIT();

        // compute on stage kt%3 : two k16 steps
        const uint32_t aS = aLd + (kt % NSTAGE) * STG_B;
        const uint32_t bS = bLd + (kt % NSTAGE) * STG_B;
#pragma unroll
        for (int k16 = 0; k16 < 2; k16++) {
            uint32_t a[4][4], b[4][2];
#pragma unroll
            for (int mt = 0; mt < 4; mt++)
                LDM_X4(a[mt][0], a[mt][1], a[mt][2], a[mt][3],
                       aS + mt * (16 * 80) + k16 * 32);
#pragma unroll
            for (int nt = 0; nt < 4; nt++)
                LDM_X2(b[nt][0], b[nt][1], bS + nt * (8 * 80) + k16 * 32);
#pragma unroll
            for (int mt = 0; mt < 4; mt++)
#pragma unroll
                for (int nt = 0; nt < 4; nt++)
                    MMA_BF16(d[mt][nt], a[mt][0], a[mt][1], a[mt][2], a[mt][3],
                             b[nt][0], b[nt][1]);
        }
    }
    CP_WAIT0();

    // ---- epilogue ----
#pragma unroll
    for (int mt = 0; mt < 4; mt++) {
#pragma unroll
        for (int half = 0; half < 2; half++) {
            const int row = row0 + wm * 64 + mt * 16 + (lane >> 2) + half * 8;
#pragma unroll
            for (int nt = 0; nt < 4; nt++) {
                const int col = n0 + wn * 32 + nt * 8 + (lane & 3) * 2;
                float v0 = d[mt][nt][half * 2 + 0] + bias[col];
                float v1 = d[mt][nt][half * 2 + 1] + bias[col + 1];
                if (ACT == 0) {
                    float2 o; o.x = v0; o.y = v1;
                    *(float2*)&Cf[(size_t)row * Ndim + col] = o;
                } else {
                    v0 = gelu_exact(v0);
                    v1 = gelu_exact(v1);
                    __nv_bfloat16 h0 = __float2bfloat16(v0);
                    __nv_bfloat16 h1 = __float2bfloat16(v1);
                    __nv_bfloat162 hp; hp.x = h0; hp.y = h1;
                    __nv_bfloat162 lp;
                    lp.x = __float2bfloat16(v0 - __bfloat162float(h0));
                    lp.y = __float2bfloat16(v1 - __bfloat162float(h1));
                    const size_t ro = (size_t)row * (size_t)(3 * cs_slab);
                    *(__nv_bfloat162*)&Cs[ro + col]               = hp;
                    *(__nv_bfloat162*)&Cs[ro + cs_slab + col]     = hp;
                    *(__nv_bfloat162*)&Cs[ro + 2 * cs_slab + col] = lp;
                }
            }
        }
    }
}

// ---------------- weight transpose + split: W[K,N] -> Wt''[N,3K] = [hi|lo|hi] -----
__global__ void wconv_kernel(const float* __restrict__ W, __nv_bfloat16* __restrict__ Wt,
                             int K, int N)
{
    __shared__ float t[32][33];
    const int n0 = blockIdx.x * 32, k0 = blockIdx.y * 32;
    for (int i = threadIdx.y; i < 32; i += 8)
        t[i][threadIdx.x] = W[(size_t)(k0 + i) * N + n0 + threadIdx.x];
    __syncthreads();
    for (int i = threadIdx.y; i < 32; i += 8) {
        int n = n0 + i, k = k0 + threadIdx.x;
        float v = t[threadIdx.x][i];
        __nv_bfloat16 hv = __float2bfloat16(v);
        __nv_bfloat16 lv = __float2bfloat16(v - __bfloat162float(hv));
        size_t ro = (size_t)n * (size_t)(3 * K);
        Wt[ro + k] = hv;
        Wt[ro + K + k] = lv;
        Wt[ro + 2 * K + k] = hv;
    }
}

// ---------------- add step embed + split: A'' = [hi|hi|lo] ----------------
__global__ void add_step_kernel(const float* __restrict__ x, const float* __restrict__ se,
                                const int* __restrict__ ts, float* __restrict__ x0,
                                __nv_bfloat16* __restrict__ xs)
{
    int i = blockIdx.x * blockDim.x + threadIdx.x;
    int step = ts[0];
    if (step > 15) step = 15;
    if (step < 0) step += 16;
    int k = i & (DM - 1);
    float v = x[i] + se[step * DM + k];
    x0[i] = v;
    __nv_bfloat16 h = __float2bfloat16(v);
    __nv_bfloat16 lo = __float2bfloat16(v - __bfloat162float(h));
    size_t ro = (size_t)(i >> 10) * KP3;
    xs[ro + k] = h;
    xs[ro + DM + k] = h;
    xs[ro + 2 * DM + k] = lo;
}

// ---------------- flash attention (fp32), epilogue writes bf16 splits -------------
__global__ void __launch_bounds__(256)
attn_kernel(const float* __restrict__ qkv, const float* __restrict__ rpb,
            __nv_bfloat16* __restrict__ outs)
{
    __shared__ __align__(16) float Qs[32 * 65];
    __shared__ __align__(16) float KPs[64 * 65];
    __shared__ __align__(16) float Vs[64 * 66];
    __shared__ float rb[127];

    const int tid = threadIdx.x;
    const int qt = blockIdx.x;
    const int h  = blockIdx.y;
    const int b  = blockIdx.z;
    const int tc = tid & 31;
    const int tr = tid >> 5;

    if (tid < 127) rb[tid] = rpb[tid];
    const int qbase = qt * 32;
    const float scale = 0.125f;

    for (int t = tid; t < 32 * 64; t += 256) {
        int r = t >> 6, c = t & 63;
        Qs[r * 65 + c] = qkv[((size_t)(b * SS + qbase + r)) * 3072 + h * 64 + c] * scale;
    }

    float m[4], l[4], acc[4][2];
#pragma unroll
    for (int i = 0; i < 4; i++) { m[i] = -1e30f; l[i] = 0.f; acc[i][0] = 0.f; acc[i][1] = 0.f; }

    for (int kt = 0; kt < 16; kt++) {
        const int kbase = kt * 64;
        __syncthreads();
        for (int t = tid; t < 64 * 64; t += 256) {
            int r = t >> 6, c = t & 63;
            size_t base = ((size_t)(b * SS + kbase + r)) * 3072 + h * 64 + c;
            KPs[r * 65 + c] = qkv[base + 1024];
            Vs [r * 66 + c] = qkv[base + 2048];
        }
        __syncthreads();

        float s0[4] = {0.f, 0.f, 0.f, 0.f};
        float s1[4] = {0.f, 0.f, 0.f, 0.f};
#pragma unroll 4
        for (int dd = 0; dd < 64; dd++) {
            float k0v = KPs[tc * 65 + dd];
            float k1v = KPs[(tc + 32) * 65 + dd];
#pragma unroll
            for (int i = 0; i < 4; i++) {
                float qv = Qs[(tr * 4 + i) * 65 + dd];
                s0[i] += qv * k0v;
                s1[i] += qv * k1v;
            }
        }
#pragma unroll
        for (int i = 0; i < 4; i++) {
            int qg = qbase + tr * 4 + i;
            int r0 = qg - (kbase + tc) + 63;       r0 = min(max(r0, 0), 126);
            int r1 = qg - (kbase + tc + 32) + 63;  r1 = min(max(r1, 0), 126);
            s0[i] += rb[r0];
            s1[i] += rb[r1];
        }
        __syncthreads();

#pragma unroll
        for (int i = 0; i < 4; i++) {
            float mt = fmaxf(s0[i], s1[i]);
#pragma unroll
            for (int o = 16; o > 0; o >>= 1) mt = fmaxf(mt, __shfl_xor_sync(0xffffffffu, mt, o));
            float mn = fmaxf(m[i], mt);
            float ci = __expf(m[i] - mn);
            float p0 = __expf(s0[i] - mn);
            float p1 = __expf(s1[i] - mn);
            float ls = p0 + p1;
#pragma unroll
            for (int o = 16; o > 0; o >>= 1) ls += __shfl_xor_sync(0xffffffffu, ls, o);
            l[i] = l[i] * ci + ls;
            m[i] = mn;
            acc[i][0] *= ci; acc[i][1] *= ci;
            KPs[(tr * 4 + i) * 65 + tc]      = p0;
            KPs[(tr * 4 + i) * 65 + tc + 32] = p1;
        }
        __syncthreads();

        const int d0 = tc * 2;
#pragma unroll 4
        for (int k = 0; k < 64; k++) {
            float2 v = *(const float2*)&Vs[k * 66 + d0];
#pragma unroll
            for (int i = 0; i < 4; i++) {
                float p = KPs[(tr * 4 + i) * 65 + k];
                acc[i][0] += p * v.x;
                acc[i][1] += p * v.y;
            }
        }
    }

#pragma unroll
    for (int i = 0; i < 4; i++) {
        float inv = 1.f / l[i];
        float v0 = acc[i][0] * inv, v1 = acc[i][1] * inv;
        size_t ro = (size_t)(b * SS + qbase + tr * 4 + i) * KP3;
        int n = h * 64 + tc * 2;
        __nv_bfloat16 h0 = __float2bfloat16(v0);
        __nv_bfloat16 h1 = __float2bfloat16(v1);
        __nv_bfloat162 hp; hp.x = h0; hp.y = h1;
        __nv_bfloat162 lp;
        lp.x = __float2bfloat16(v0 - __bfloat162float(h0));
        lp.y = __float2bfloat16(v1 - __bfloat162float(h1));
        *(__nv_bfloat162*)&outs[ro + n]          = hp;
        *(__nv_bfloat162*)&outs[ro + DM + n]     = hp;
        *(__nv_bfloat162*)&outs[ro + 2 * DM + n] = lp;
    }
}

// ---------------- residual + layernorm (SPLIT=1: also write bf16 splits) ---------
template <int SPLIT>
__global__ void __launch_bounds__(256)
ln_res_kernel(const float* __restrict__ a, const float* __restrict__ r,
              const float* __restrict__ g, const float* __restrict__ bt,
              float* __restrict__ out, __nv_bfloat16* __restrict__ outs)
{
    __shared__ float red[8];
    const int row = blockIdx.x;
    const int tid = threadIdx.x;
    const float* pa = a + (size_t)row * DM;
    const float* pr = r + (size_t)row * DM;

    float v[4];
    float sum = 0.f;
#pragma unroll
    for (int j = 0; j < 4; j++) {
        int c = tid + j * 256;
        v[j] = pa[c] + pr[c];
        sum += v[j];
    }
#pragma unroll
    for (int o = 16; o > 0; o >>= 1) sum += __shfl_xor_sync(0xffffffffu, sum, o);
    if ((tid & 31) == 0) red[tid >> 5] = sum;
    __syncthreads();
    float tot = 0.f;
#pragma unroll
    for (int w = 0; w < 8; w++) tot += red[w];
    const float mean = tot * (1.f / (float)DM);

    float sq = 0.f;
#pragma unroll
    for (int j = 0; j < 4; j++) { float dd = v[j] - mean; sq += dd * dd; }
    __syncthreads();
#pragma unroll
    for (int o = 16; o > 0; o >>= 1) sq += __shfl_xor_sync(0xffffffffu, sq, o);
    if ((tid & 31) == 0) red[tid >> 5] = sq;
    __syncthreads();
    float vtot = 0.f;
#pragma unroll
    for (int w = 0; w < 8; w++) vtot += red[w];
    const float inv = rsqrtf(vtot * (1.f / (float)DM) + 1e-5f);

#pragma unroll
    for (int j = 0; j < 4; j++) {
        int c = tid + j * 256;
        float o = (v[j] - mean) * inv * g[c] + bt[c];
        out[(size_t)row * DM + c] = o;
        if (SPLIT) {
            __nv_bfloat16 h = __float2bfloat16(o);
            __nv_bfloat16 lo = __float2bfloat16(o - __bfloat162float(h));
            size_t ro = (size_t)row * KP3;
            outs[ro + c] = h;
            outs[ro + DM + c] = h;
            outs[ro + 2 * DM + c] = lo;
        }
    }
}

// ---------------- host ----------------
extern "C" void kernel_launch(void* const* d_in, const int* in_sizes, int n_in,
                              void* d_out, int out_size)
{
    const float* x     = (const float*)d_in[0];
    const float* se    = (const float*)d_in[1];
    const float* qkv_w = (const float*)d_in[2];
    const float* qkv_b = (const float*)d_in[3];
    const float* out_w = (const float*)d_in[4];
    const float* out_b = (const float*)d_in[5];
    const float* rpb   = (const float*)d_in[6];
    const float* w1    = (const float*)d_in[7];
    const float* b1    = (const float*)d_in[8];
    const float* w2    = (const float*)d_in[9];
    const float* b2    = (const float*)d_in[10];
    const float* ln1g  = (const float*)d_in[11];
    const float* ln1b  = (const float*)d_in[12];
    const float* ln2g  = (const float*)d_in[13];
    const float* ln2b  = (const float*)d_in[14];
    const int*   ts    = (const int*)d_in[15];
    float* out = (float*)d_out;

    float *x0, *qkv, *proj, *x1, *ffn;
    __nv_bfloat16 *x0s, *attns, *x1s, *hs, *wqkvs, *wouts, *w1s, *w2s;
    cudaGetSymbolAddress((void**)&x0,   g_x0);
    cudaGetSymbolAddress((void**)&qkv,  g_qkv);
    cudaGetSymbolAddress((void**)&proj, g_proj);
    cudaGetSymbolAddress((void**)&x1,   g_x1);
    cudaGetSymbolAddress((void**)&ffn,  g_ffn);
    cudaGetSymbolAddress((void**)&x0s,   g_x0s);
    cudaGetSymbolAddress((void**)&attns, g_attns);
    cudaGetSymbolAddress((void**)&x1s,   g_x1s);
    cudaGetSymbolAddress((void**)&hs,    g_hs);
    cudaGetSymbolAddress((void**)&wqkvs, g_wqkvs);
    cudaGetSymbolAddress((void**)&wouts, g_wouts);
    cudaGetSymbolAddress((void**)&w1s,   g_w1s);
    cudaGetSymbolAddress((void**)&w2s,   g_w2s);

    cudaFuncSetAttribute(gemm_mma<0>, cudaFuncAttributeMaxDynamicSharedMemorySize, GSMEM);
    cudaFuncSetAttribute(gemm_mma<1>, cudaFuncAttributeMaxDynamicSharedMemorySize, GSMEM);

    // weight conversions (transpose + hi/lo split)
    wconv_kernel<<<dim3(3 * DM / 32, DM / 32),  dim3(32, 8)>>>(qkv_w, wqkvs, DM, 3 * DM);
    wconv_kernel<<<dim3(DM / 32, DM / 32),      dim3(32, 8)>>>(out_w, wouts, DM, DM);
    wconv_kernel<<<dim3(DFF / 32, DM / 32),     dim3(32, 8)>>>(w1, w1s, DM, DFF);
    wconv_kernel<<<dim3(DM / 32, DFF / 32),     dim3(32, 8)>>>(w2, w2s, DFF, DM);

    // 1) x0 = x + step_embed ; split
    add_step_kernel<<<(MTOK * DM) / 256, 256>>>(x, se, ts, x0, x0s);

    // 2) qkv = x0 @ qkv_w + b
    gemm_mma<0><<<dim3(3 * DM / 128, MTOK / 128), 256, GSMEM>>>(
        x0s, wqkvs, qkv_b, qkv, nullptr, 3 * DM, KP3, 0);

    // 3) attention -> attns (split)
    attn_kernel<<<dim3(SS / 32, NH, BB), 256>>>(qkv, rpb, attns);

    // 4) proj = attn @ out_w + b
    gemm_mma<0><<<dim3(DM / 128, MTOK / 128), 256, GSMEM>>>(
        attns, wouts, out_b, proj, nullptr, DM, KP3, 0);

    // 5) x1 = LN(x0 + proj) ; split
    ln_res_kernel<1><<<MTOK, 256>>>(x0, proj, ln1g, ln1b, x1, x1s);

    // 6) h = gelu(x1 @ w1 + b1) -> hs (split)
    gemm_mma<1><<<dim3(DFF / 128, MTOK / 128), 256, GSMEM>>>(
        x1s, w1s, b1, nullptr, hs, DFF, KP3, DFF);

    // 7) ffn = h @ w2 + b2
    gemm_mma<0><<<dim3(DM / 128, MTOK / 128), 256, GSMEM>>>(
        hs, w2s, b2, ffn, nullptr, DM, KP3FF, 0);

    // 8) out = LN(x1 + ffn)
    ln_res_kernel<0><<<MTOK, 256>>>(x1, ffn, ln2g, ln2b, out, nullptr);
}